// round 5
// baseline (speedup 1.0000x reference)
#include <cuda_runtime.h>
#include <math.h>

#define N_   8
#define C_   64
#define H_   256
#define W_   256
#define K2_  9
#define GK2_ 72
#define QELEMS (H_ * W_ / 4)      // floats per quarter plane

// scratch (no cudaMalloc allowed)
__device__ float g_part[N_ * C_ * 4];   // quarter-plane raw sums

// ---------------------------------------------------------------------------
// Combo kernel: pool phase for sample pool_n (256 blocks) and/or main phase
// for sample main_n (256 blocks). When both active, grid=512, interleaved by
// blockIdx parity so both phases spread across SMs and overlap.
// Main phase recomputes lf weights per block from g_part (cheap, redundant),
// and reads its sample's x entirely from L2 (pulled in by previous launch).
// ---------------------------------------------------------------------------
__global__ __launch_bounds__(256) void combo_kernel(
        const float* __restrict__ x,
        const float* __restrict__ conv_w,
        const float* __restrict__ bn_gamma,
        const float* __restrict__ bn_beta,
        const float* __restrict__ bn_mean,
        const float* __restrict__ bn_var,
        const float* __restrict__ lamb_l,
        const float* __restrict__ lamb_h,
        const float* __restrict__ inside_all,
        float* __restrict__ out,
        int pool_n, int main_n) {
    const int tid = threadIdx.x;
    int type, idx;
    if (pool_n >= 0 && main_n >= 0) { type = blockIdx.x & 1; idx = blockIdx.x >> 1; }
    else if (pool_n >= 0)           { type = 0;              idx = blockIdx.x; }
    else                            { type = 1;              idx = blockIdx.x; }

    if (type == 0) {
        // ---------------- pool phase: quarter-plane sum --------------------
        const int plane = idx >> 2;
        const int quad  = idx & 3;
        const size_t off = (size_t)(pool_n * C_ + plane) * (H_ * W_) + (size_t)quad * QELEMS;
        const float4* xv = (const float4*)(x + off);
        float s = 0.f;
        #pragma unroll
        for (int i = 0; i < 16; ++i) {
            float4 v = __ldg(&xv[tid + i * 256]);
            s += (v.x + v.y) + (v.z + v.w);
        }
        #pragma unroll
        for (int o = 16; o; o >>= 1) s += __shfl_down_sync(0xffffffffu, s, o);
        __shared__ float ws[8];
        if ((tid & 31) == 0) ws[tid >> 5] = s;
        __syncthreads();
        if (tid < 8) {
            float t = ws[tid];
            #pragma unroll
            for (int o = 4; o; o >>= 1) t += __shfl_down_sync(0xffu, t, o);
            if (tid == 0) g_part[(pool_n * C_ + plane) * 4 + quad] = t;
        }
        return;
    }

    // ---------------- main phase: lf + 3x3 reflect stencil ------------------
    const int tile = idx & 3;            // 64-row band
    const int c    = idx >> 2;
    const int n    = main_n;

    __shared__ float ps[C_];
    __shared__ float wlf[K2_];

    if (tid < C_) {
        const float* p = g_part + (n * C_ + tid) * 4;
        ps[tid] = (p[0] + p[1] + p[2] + p[3]) * (1.f / (H_ * W_));
    }
    __syncthreads();
    if (tid < K2_) {
        const int j = (c >> 3) * K2_ + tid;      // g*9 + tap
        const float* w = conv_w + j * C_;
        float acc = 0.f;
        #pragma unroll
        for (int cc = 0; cc < C_; ++cc) acc = fmaf(ps[cc], w[cc], acc);
        const float inv = rsqrtf(bn_var[j] + 1e-5f);
        const float v = (acc - bn_mean[j]) * (bn_gamma[j] * inv) + bn_beta[j];
        wlf[tid] = tanhf(v);
    }
    __syncthreads();

    const int warp = tid >> 5;
    const int lane = tid & 31;
    const int yr0  = tile * 64 + warp * 8;       // 8 output rows per warp

    const size_t plane_off = (size_t)(n * C_ + c) * H_ * W_;
    const float* xp = x + plane_off;

    const float w0 = wlf[0], w1 = wlf[1], w2 = wlf[2];
    const float w3 = wlf[3], w4 = wlf[4], w5 = wlf[5];
    const float w6 = wlf[6], w7 = wlf[7], w8 = wlf[8];

    const float ll  = __ldg(lamb_l + c);
    const float lh1 = __ldg(lamb_h + c) + 1.f;
    const float ia  = __ldg(inside_all + c);
    const float A   = (ia + 1.f) * ll;
    const float Bc  = -ia * ps[c] * ll;

    // window cols: 8*lane-1 .. 8*lane+8  (10 floats)
    float win[3][10];
    #define LOADROW(GR, D) do {                                            \
        int _g = (GR);                                                     \
        _g = _g < 0 ? -_g : (_g >= H_ ? 2 * H_ - 2 - _g : _g);             \
        const float4* _p = (const float4*)(xp + (size_t)_g * W_);          \
        float4 _L = __ldg(&_p[2 * lane]);                                  \
        float4 _R = __ldg(&_p[2 * lane + 1]);                              \
        float _lf = __shfl_up_sync(0xffffffffu, _R.w, 1);                  \
        float _rt = __shfl_down_sync(0xffffffffu, _L.x, 1);                \
        if (lane == 0)  _lf = _L.y;   /* reflect col -1 -> col 1   */      \
        if (lane == 31) _rt = _R.z;   /* reflect col 256 -> col 254 */     \
        (D)[0] = _lf;                                                      \
        (D)[1] = _L.x; (D)[2] = _L.y; (D)[3] = _L.z; (D)[4] = _L.w;        \
        (D)[5] = _R.x; (D)[6] = _R.y; (D)[7] = _R.z; (D)[8] = _R.w;        \
        (D)[9] = _rt;                                                      \
    } while (0)

    LOADROW(yr0 - 1, win[0]);
    LOADROW(yr0,     win[1]);

    float* ob = out + plane_off + (size_t)yr0 * W_ + 8 * lane;

    #pragma unroll
    for (int k = 0; k < 8; ++k) {
        LOADROW(yr0 + 1 + k, win[(k + 2) % 3]);
        const float* t0 = win[k % 3];
        const float* t1 = win[(k + 1) % 3];
        const float* t2 = win[(k + 2) % 3];
        float o[8];
        #pragma unroll
        for (int j = 0; j < 8; ++j) {
            float acc;
            acc = w0 * t0[j];
            acc = fmaf(w1, t0[j + 1], acc);
            acc = fmaf(w2, t0[j + 2], acc);
            acc = fmaf(w3, t1[j],     acc);
            acc = fmaf(w4, t1[j + 1], acc);
            acc = fmaf(w5, t1[j + 2], acc);
            acc = fmaf(w6, t2[j],     acc);
            acc = fmaf(w7, t2[j + 1], acc);
            acc = fmaf(w8, t2[j + 2], acc);
            o[j] = fmaf(acc, A, fmaf(t1[j + 1], lh1, Bc));
        }
        float4* op = (float4*)(ob + (size_t)k * W_);
        __stcs(op,     make_float4(o[0], o[1], o[2], o[3]));
        __stcs(op + 1, make_float4(o[4], o[5], o[6], o[7]));
    }
    #undef LOADROW
}

// ---------------------------------------------------------------------------
extern "C" void kernel_launch(void* const* d_in, const int* in_sizes, int n_in,
                              void* d_out, int out_size) {
    const float* x          = (const float*)d_in[0];
    const float* conv_w     = (const float*)d_in[1];
    const float* bn_gamma   = (const float*)d_in[2];
    const float* bn_beta    = (const float*)d_in[3];
    const float* bn_mean    = (const float*)d_in[4];
    const float* bn_var     = (const float*)d_in[5];
    const float* lamb_l     = (const float*)d_in[6];
    const float* lamb_h     = (const float*)d_in[7];
    const float* inside_all = (const float*)d_in[8];
    float* out = (float*)d_out;

    // software pipeline: pool(s) overlaps main(s-1) inside each launch
    combo_kernel<<<256, 256>>>(x, conv_w, bn_gamma, bn_beta, bn_mean, bn_var,
                               lamb_l, lamb_h, inside_all, out, 0, -1);
    for (int s = 1; s < N_; ++s)
        combo_kernel<<<512, 256>>>(x, conv_w, bn_gamma, bn_beta, bn_mean, bn_var,
                                   lamb_l, lamb_h, inside_all, out, s, s - 1);
    combo_kernel<<<256, 256>>>(x, conv_w, bn_gamma, bn_beta, bn_mean, bn_var,
                               lamb_l, lamb_h, inside_all, out, -1, N_ - 1);
}

// round 6
// speedup vs baseline: 1.4935x; 1.4935x over previous
#include <cuda_runtime.h>
#include <math.h>

#define N_   8
#define C_   64
#define H_   256
#define W_   256
#define K2_  9
#define GK2_ 72
#define NBLK 512
#define QELEMS (H_ * W_ / 4)

// scratch (no cudaMalloc allowed)
__device__ float g_part[N_ * C_ * 4];            // quarter-plane raw sums
__device__ unsigned long long g_bar = 0ULL;      // monotonic barrier ticket

__global__ __launch_bounds__(256, 4) void fused_kernel(
        const float* __restrict__ x,
        const float* __restrict__ conv_w,
        const float* __restrict__ bn_gamma,
        const float* __restrict__ bn_beta,
        const float* __restrict__ bn_mean,
        const float* __restrict__ bn_var,
        const float* __restrict__ lamb_l,
        const float* __restrict__ lamb_h,
        const float* __restrict__ inside_all,
        float* __restrict__ out) {
    const int tid  = threadIdx.x;
    const int warp = tid >> 5;
    const int lane = tid & 31;

    __shared__ float ws[8];
    __shared__ float ps[C_];
    __shared__ float wlf[K2_];
    __shared__ unsigned long long bar_target;

    // ===================== phase 1: pool (forward stream) ===================
    #pragma unroll
    for (int it = 0; it < 4; ++it) {
        const int item = blockIdx.x + (it << 9);         // 0..2047
        const float4* xv = (const float4*)(x + (size_t)item * QELEMS);
        float s = 0.f;
        #pragma unroll
        for (int i = 0; i < 16; ++i) {
            float4 v = __ldg(&xv[tid + i * 256]);
            s += (v.x + v.y) + (v.z + v.w);
        }
        #pragma unroll
        for (int o = 16; o; o >>= 1) s += __shfl_down_sync(0xffffffffu, s, o);
        if (lane == 0) ws[warp] = s;
        __syncthreads();
        if (tid < 8) {
            float t = ws[tid];
            #pragma unroll
            for (int o = 4; o; o >>= 1) t += __shfl_down_sync(0xffu, t, o);
            if (tid == 0) g_part[item] = t;
        }
        __syncthreads();
    }

    // ===================== grid barrier (monotonic, replay-safe) ============
    if (tid == 0) {
        __threadfence();
        unsigned long long t = atomicAdd(&g_bar, 1ULL);
        bar_target = (t / NBLK + 1ULL) * (unsigned long long)NBLK;
    }
    __syncthreads();
    if (tid == 0) {
        while (*((volatile unsigned long long*)&g_bar) < bar_target)
            __nanosleep(64);
    }
    __syncthreads();
    __threadfence();

    // ===================== phase 2: stencil (reverse stream) ================
    #pragma unroll 1
    for (int it = 0; it < 4; ++it) {
        const int item  = 2047 - (blockIdx.x + (it << 9));
        const int plane = item >> 2;                     // n*C + c
        const int tile  = item & 3;                      // 64-row band
        const int n     = plane >> 6;
        const int c     = plane & 63;

        __syncthreads();
        if (tid < C_) {
            const float* p = g_part + (n * C_ + tid) * 4;
            ps[tid] = (__ldcg(p + 0) + __ldcg(p + 1) + __ldcg(p + 2) + __ldcg(p + 3))
                      * (1.f / (H_ * W_));
        }
        __syncthreads();
        if (tid < K2_) {
            const int j = (c >> 3) * K2_ + tid;
            const float* w = conv_w + j * C_;
            float acc = 0.f;
            #pragma unroll
            for (int cc = 0; cc < C_; ++cc) acc = fmaf(ps[cc], w[cc], acc);
            const float inv = rsqrtf(bn_var[j] + 1e-5f);
            const float v = (acc - bn_mean[j]) * (bn_gamma[j] * inv) + bn_beta[j];
            wlf[tid] = tanhf(v);
        }
        __syncthreads();

        const int yr0 = tile * 64 + warp * 8;            // 8 output rows/warp
        const size_t plane_off = (size_t)plane * (H_ * W_);
        const float* xp = x + plane_off;

        const float w0 = wlf[0], w1 = wlf[1], w2 = wlf[2];
        const float w3 = wlf[3], w4 = wlf[4], w5 = wlf[5];
        const float w6 = wlf[6], w7 = wlf[7], w8 = wlf[8];

        const float ll  = __ldg(lamb_l + c);
        const float lh1 = __ldg(lamb_h + c) + 1.f;
        const float ia  = __ldg(inside_all + c);
        const float A   = (ia + 1.f) * ll;
        const float Bc  = -ia * ps[c] * ll;

        float win[3][10];
        #define LOADROW(GR, D) do {                                        \
            int _g = (GR);                                                 \
            _g = _g < 0 ? -_g : (_g >= H_ ? 2 * H_ - 2 - _g : _g);         \
            const float4* _p = (const float4*)(xp + (size_t)_g * W_);      \
            float4 _L = __ldg(&_p[2 * lane]);                              \
            float4 _R = __ldg(&_p[2 * lane + 1]);                          \
            float _lf = __shfl_up_sync(0xffffffffu, _R.w, 1);              \
            float _rt = __shfl_down_sync(0xffffffffu, _L.x, 1);            \
            if (lane == 0)  _lf = _L.y;                                    \
            if (lane == 31) _rt = _R.z;                                    \
            (D)[0] = _lf;                                                  \
            (D)[1] = _L.x; (D)[2] = _L.y; (D)[3] = _L.z; (D)[4] = _L.w;    \
            (D)[5] = _R.x; (D)[6] = _R.y; (D)[7] = _R.z; (D)[8] = _R.w;    \
            (D)[9] = _rt;                                                  \
        } while (0)

        LOADROW(yr0 - 1, win[0]);
        LOADROW(yr0,     win[1]);

        float* ob = out + plane_off + (size_t)yr0 * W_ + 8 * lane;

        #pragma unroll
        for (int k = 0; k < 8; ++k) {
            LOADROW(yr0 + 1 + k, win[(k + 2) % 3]);
            const float* t0 = win[k % 3];
            const float* t1 = win[(k + 1) % 3];
            const float* t2 = win[(k + 2) % 3];
            float o[8];
            #pragma unroll
            for (int j = 0; j < 8; ++j) {
                float acc;
                acc = w0 * t0[j];
                acc = fmaf(w1, t0[j + 1], acc);
                acc = fmaf(w2, t0[j + 2], acc);
                acc = fmaf(w3, t1[j],     acc);
                acc = fmaf(w4, t1[j + 1], acc);
                acc = fmaf(w5, t1[j + 2], acc);
                acc = fmaf(w6, t2[j],     acc);
                acc = fmaf(w7, t2[j + 1], acc);
                acc = fmaf(w8, t2[j + 2], acc);
                o[j] = fmaf(acc, A, fmaf(t1[j + 1], lh1, Bc));
            }
            float4* op = (float4*)(ob + (size_t)k * W_);
            __stcs(op,     make_float4(o[0], o[1], o[2], o[3]));
            __stcs(op + 1, make_float4(o[4], o[5], o[6], o[7]));
        }
        #undef LOADROW
    }
}

// ---------------------------------------------------------------------------
extern "C" void kernel_launch(void* const* d_in, const int* in_sizes, int n_in,
                              void* d_out, int out_size) {
    const float* x          = (const float*)d_in[0];
    const float* conv_w     = (const float*)d_in[1];
    const float* bn_gamma   = (const float*)d_in[2];
    const float* bn_beta    = (const float*)d_in[3];
    const float* bn_mean    = (const float*)d_in[4];
    const float* bn_var     = (const float*)d_in[5];
    const float* lamb_l     = (const float*)d_in[6];
    const float* lamb_h     = (const float*)d_in[7];
    const float* inside_all = (const float*)d_in[8];
    float* out = (float*)d_out;

    fused_kernel<<<NBLK, 256>>>(x, conv_w, bn_gamma, bn_beta, bn_mean, bn_var,
                                lamb_l, lamb_h, inside_all, out);
}

// round 8
// speedup vs baseline: 1.5366x; 1.0288x over previous
#include <cuda_runtime.h>
#include <math.h>

#define N_   8
#define C_   64
#define H_   256
#define W_   256
#define K2_  9
#define NBLK 512
#define QELEMS (H_ * W_ / 4)

// scratch (no cudaMalloc allowed); all counters monotonic => graph-replay safe
__device__ float g_part[N_ * C_ * 4];            // quarter-plane raw sums
__device__ unsigned int g_done[N_];              // pool completion per sample
__device__ unsigned int g_epoch_blk[NBLK];       // per-block replay counter

// ---------------------------------------------------------------------------
// Stencil for one 64-row x 256-col tile. Each warp: 4 tasks; a task is a
// 4-row x 128-col half-band. All 6 input rows preloaded (12+ independent LDG,
// MLP high) before SHFL/compute. Reflect padding resolved in-register.
// ---------------------------------------------------------------------------
__device__ __forceinline__ void stencil_tile(
        const float* __restrict__ x, float* __restrict__ out,
        int plane, int tile, int c, int warp, int lane,
        const float* wlf, const float* ps,
        const float* __restrict__ lamb_l,
        const float* __restrict__ lamb_h,
        const float* __restrict__ inside_all) {
    const size_t plane_off = (size_t)plane * (H_ * W_);
    const float* xp = x + plane_off;

    const float w0 = wlf[0], w1 = wlf[1], w2 = wlf[2];
    const float w3 = wlf[3], w4 = wlf[4], w5 = wlf[5];
    const float w6 = wlf[6], w7 = wlf[7], w8 = wlf[8];

    const float ll  = __ldg(lamb_l + c);
    const float lh1 = __ldg(lamb_h + c) + 1.f;
    const float ia  = __ldg(inside_all + c);
    const float A   = (ia + 1.f) * ll;
    const float Bc  = -ia * ps[c] * ll;

    #pragma unroll 1
    for (int i = 0; i < 4; ++i) {
        const int T    = warp * 4 + i;      // 0..31
        const int band = T >> 1;            // 0..15 -> 4-row band
        const int half = T & 1;             // 128-col half
        const int y0   = tile * 64 + band * 4;
        const int cb   = half * 128 + lane * 4;

        float win[6][6];
        #pragma unroll
        for (int r = 0; r < 6; ++r) {
            int g = y0 - 1 + r;
            g = g < 0 ? 1 : (g >= H_ ? 2 * H_ - 2 - g : g);
            const float* rp = xp + (size_t)g * W_;
            float4 v = __ldg((const float4*)(rp + cb));
            float  e = __ldg(rp + (half ? 127 : 128));   // uniform boundary scalar
            float lf = __shfl_up_sync(0xffffffffu, v.w, 1);
            float rt = __shfl_down_sync(0xffffffffu, v.x, 1);
            if (half == 0) {
                if (lane == 0)  lf = v.y;   // reflect col -1 -> col 1
                if (lane == 31) rt = e;     // col 128 from other half
            } else {
                if (lane == 0)  lf = e;     // col 127 from other half
                if (lane == 31) rt = v.z;   // reflect col 256 -> col 254
            }
            win[r][0] = lf;
            win[r][1] = v.x; win[r][2] = v.y; win[r][3] = v.z; win[r][4] = v.w;
            win[r][5] = rt;
        }

        float* ob = out + plane_off + (size_t)y0 * W_ + cb;
        #pragma unroll
        for (int k = 0; k < 4; ++k) {
            float o[4];
            #pragma unroll
            for (int j = 0; j < 4; ++j) {
                float acc;
                acc = w0 * win[k][j];
                acc = fmaf(w1, win[k][j + 1], acc);
                acc = fmaf(w2, win[k][j + 2], acc);
                acc = fmaf(w3, win[k + 1][j],     acc);
                acc = fmaf(w4, win[k + 1][j + 1], acc);
                acc = fmaf(w5, win[k + 1][j + 2], acc);
                acc = fmaf(w6, win[k + 2][j],     acc);
                acc = fmaf(w7, win[k + 2][j + 1], acc);
                acc = fmaf(w8, win[k + 2][j + 2], acc);
                o[j] = fmaf(acc, A, fmaf(win[k + 1][j + 1], lh1, Bc));
            }
            __stcs((float4*)(ob + (size_t)k * W_),
                   make_float4(o[0], o[1], o[2], o[3]));
        }
    }
}

__global__ __launch_bounds__(256, 4) void fused_kernel(
        const float* __restrict__ x,
        const float* __restrict__ conv_w,
        const float* __restrict__ bn_gamma,
        const float* __restrict__ bn_beta,
        const float* __restrict__ bn_mean,
        const float* __restrict__ bn_var,
        const float* __restrict__ lamb_l,
        const float* __restrict__ lamb_h,
        const float* __restrict__ inside_all,
        float* __restrict__ out) {
    const int b    = blockIdx.x;
    const int tid  = threadIdx.x;
    const int warp = tid >> 5;
    const int lane = tid & 31;

    __shared__ float ws[8];
    __shared__ float ps[C_];
    __shared__ float wlf[K2_];
    __shared__ unsigned int sh_target;

    if (tid == 0)
        sh_target = (atomicAdd(&g_epoch_blk[b], 1u) + 1u) * 256u;
    __syncthreads();
    const unsigned int target = sh_target;

    // ---------------- pool step: quarter-plane sum of item (q<<9)|b ---------
    #define POOL_STEP(q) do {                                                 \
        const int item = ((q) << 9) | b;                                      \
        const float4* xv = (const float4*)(x + (size_t)item * QELEMS);        \
        float s = 0.f;                                                        \
        _Pragma("unroll")                                                     \
        for (int i = 0; i < 16; ++i) {                                        \
            float4 v = __ldg(&xv[tid + i * 256]);                             \
            s += (v.x + v.y) + (v.z + v.w);                                   \
        }                                                                     \
        _Pragma("unroll")                                                     \
        for (int o = 16; o; o >>= 1) s += __shfl_down_sync(0xffffffffu, s, o);\
        if (lane == 0) ws[warp] = s;                                          \
        __syncthreads();                                                      \
        if (tid == 0) {                                                       \
            float t = ws[0] + ws[1] + ws[2] + ws[3]                           \
                    + ws[4] + ws[5] + ws[6] + ws[7];                          \
            g_part[item] = t;                                                 \
            __threadfence();                                                  \
            atomicAdd(&g_done[item >> 8], 1u);                                \
        }                                                                     \
        __syncthreads();                                                      \
    } while (0)

    // ---------------- stencil step for item (q<<9)|b -------------------------
    #define MAIN_STEP(q) do {                                                 \
        const int j     = ((q) << 9) | b;                                     \
        const int smp   = j >> 8;                                             \
        const int plane = j >> 2;                                             \
        const int tile  = j & 3;                                              \
        const int c     = plane & 63;                                         \
        if (tid == 0) {                                                       \
            while (*((volatile unsigned int*)&g_done[smp]) < target)          \
                __nanosleep(32);                                              \
        }                                                                     \
        __syncthreads();                                                      \
        __threadfence();                                                      \
        if (tid < C_) {                                                       \
            const float* p = g_part + ((plane & ~63) | tid) * 4;              \
            ps[tid] = (__ldcg(p) + __ldcg(p + 1) + __ldcg(p + 2)              \
                       + __ldcg(p + 3)) * (1.f / (H_ * W_));                  \
        }                                                                     \
        __syncthreads();                                                      \
        if (tid < K2_) {                                                      \
            const int jj = (c >> 3) * K2_ + tid;                              \
            const float* wv = conv_w + jj * C_;                               \
            float acc = 0.f;                                                  \
            _Pragma("unroll")                                                 \
            for (int cc = 0; cc < C_; ++cc) acc = fmaf(ps[cc], wv[cc], acc);  \
            const float inv = rsqrtf(bn_var[jj] + 1e-5f);                     \
            const float v = (acc - bn_mean[jj]) * (bn_gamma[jj] * inv)        \
                            + bn_beta[jj];                                    \
            wlf[tid] = tanhf(v);                                              \
        }                                                                     \
        __syncthreads();                                                      \
        stencil_tile(x, out, plane, tile, c, warp, lane,                      \
                     wlf, ps, lamb_l, lamb_h, inside_all);                    \
        __syncthreads();                                                      \
    } while (0)

    POOL_STEP(0);
    POOL_STEP(1);
    MAIN_STEP(0);
    POOL_STEP(2);
    MAIN_STEP(1);
    POOL_STEP(3);
    MAIN_STEP(2);
    MAIN_STEP(3);

    #undef POOL_STEP
    #undef MAIN_STEP
}

// ---------------------------------------------------------------------------
extern "C" void kernel_launch(void* const* d_in, const int* in_sizes, int n_in,
                              void* d_out, int out_size) {
    const float* x          = (const float*)d_in[0];
    const float* conv_w     = (const float*)d_in[1];
    const float* bn_gamma   = (const float*)d_in[2];
    const float* bn_beta    = (const float*)d_in[3];
    const float* bn_mean    = (const float*)d_in[4];
    const float* bn_var     = (const float*)d_in[5];
    const float* lamb_l     = (const float*)d_in[6];
    const float* lamb_h     = (const float*)d_in[7];
    const float* inside_all = (const float*)d_in[8];
    float* out = (float*)d_out;

    fused_kernel<<<NBLK, 256>>>(x, conv_w, bn_gamma, bn_beta, bn_mean, bn_var,
                                lamb_l, lamb_h, inside_all, out);
}